// round 2
// baseline (speedup 1.0000x reference)
#include <cuda_runtime.h>
#include <cstdint>

#define MTOK 8192
#define DDIM 4096
#define ODIM 4096
#define NEXP 8
#define RRNK 16
#define ERD  128
#define NLOG 15
#define SCALING 2.0f

// Scratch (allocation-free rule: __device__ globals)
__device__ float g_w[MTOK * NEXP];      // 256 KB: per-token expert combine weights
__device__ float g_hw[MTOK * ERD];      // 4 MB:  w-scaled low-rank activations (incl SCALING)
__device__ float g_Bcat[ERD * ODIM];    // 2 MB:  B transposed to [er][o]

typedef unsigned long long u64;

__device__ __forceinline__ u64 pack2(float lo, float hi) {
    u64 r; asm("mov.b64 %0, {%1,%2};" : "=l"(r) : "f"(lo), "f"(hi)); return r;
}
__device__ __forceinline__ void unpack2(u64 v, float& lo, float& hi) {
    asm("mov.b64 {%0,%1}, %2;" : "=f"(lo), "=f"(hi) : "l"(v));
}
// packed dual-FMA: d.lo += a.lo*b.lo ; d.hi += a.hi*b.hi   (full-rate vs half-rate FFMA-3reg)
__device__ __forceinline__ void fma2(u64& d, u64 a, u64 b) {
    asm("fma.rn.f32x2 %0, %1, %2, %0;" : "+l"(d) : "l"(a), "l"(b));
}

// ---------------------------------------------------------------------------
// Router: logits -> softmax -> top-8 of 15 -> per-expert combine weight w[t][e]
// ---------------------------------------------------------------------------
__global__ void router_kernel(const float* __restrict__ x,
                              const float* __restrict__ rW,
                              const float* __restrict__ rb,
                              const int* __restrict__ emap) {
    int t = blockIdx.x;
    int tid = threadIdx.x; // 128 threads
    const float4* xr = (const float4*)(x + (size_t)t * DDIM);
    float acc[NLOG];
#pragma unroll
    for (int n = 0; n < NLOG; n++) acc[n] = 0.f;
    for (int d4 = tid; d4 < DDIM / 4; d4 += 128) {
        float4 xv = xr[d4];
#pragma unroll
        for (int n = 0; n < NLOG; n++) {
            float4 wv = ((const float4*)(rW + (size_t)n * DDIM))[d4];
            acc[n] += xv.x * wv.x + xv.y * wv.y + xv.z * wv.z + xv.w * wv.w;
        }
    }
    __shared__ float red[NLOG][128];
#pragma unroll
    for (int n = 0; n < NLOG; n++) red[n][tid] = acc[n];
    __syncthreads();
#pragma unroll
    for (int s = 64; s > 0; s >>= 1) {
        if (tid < s) {
#pragma unroll
            for (int n = 0; n < NLOG; n++) red[n][tid] += red[n][tid + s];
        }
        __syncthreads();
    }
    if (tid == 0) {
        float p[NLOG];
        float mx = -1e30f;
#pragma unroll
        for (int n = 0; n < NLOG; n++) {
            p[n] = red[n][0] + rb[n];
            mx = fmaxf(mx, p[n]);
        }
        float s = 0.f;
#pragma unroll
        for (int n = 0; n < NLOG; n++) { p[n] = expf(p[n] - mx); s += p[n]; }
        float inv = 1.f / s;
#pragma unroll
        for (int n = 0; n < NLOG; n++) p[n] *= inv;
        float wacc[NEXP];
#pragma unroll
        for (int e = 0; e < NEXP; e++) wacc[e] = 0.f;
        bool used[NLOG];
#pragma unroll
        for (int n = 0; n < NLOG; n++) used[n] = false;
        // top-8 (strict > keeps lowest index on ties, matching jax.lax.top_k)
        for (int k = 0; k < NEXP; k++) {
            int best = 0; float bv = -1e30f;
            for (int n = 0; n < NLOG; n++)
                if (!used[n] && p[n] > bv) { bv = p[n]; best = n; }
            used[best] = true;
            wacc[emap[best]] += bv;
        }
#pragma unroll
        for (int e = 0; e < NEXP; e++) g_w[t * NEXP + e] = wacc[e];
    }
}

// ---------------------------------------------------------------------------
// Bcat[er][o] = B[e][o][r]
// ---------------------------------------------------------------------------
__global__ void bcat_kernel(const float* __restrict__ Bm) {
    int idx = blockIdx.x * blockDim.x + threadIdx.x;
    if (idx < ERD * ODIM) {
        int er = idx >> 12;       // / 4096
        int o  = idx & 4095;
        int e = er >> 4, r = er & 15;
        g_Bcat[idx] = Bm[((size_t)e * ODIM + o) * RRNK + r];
    }
}

// ---------------------------------------------------------------------------
// hw[t][er] = (x[t] . A[e][r]) * w[t][e] * SCALING
// GEMM M=8192, N=128, K=4096 ; tile 64x128x16, 256 threads, TM=4 TN=8
// ---------------------------------------------------------------------------
__global__ __launch_bounds__(256, 2)
void hw_kernel(const float* __restrict__ x, const float* __restrict__ A) {
    __shared__ float As[16][64];
    __shared__ float Bs[16][128];
    int m0 = blockIdx.x * 64;
    int tid = threadIdx.x;
    int lk = (tid & 3) * 4;   // 0,4,8,12
    int lm = tid >> 2;        // 0..63
    int tm0 = (tid >> 4) * 4;
    int tn0 = (tid & 15) * 8;
    u64 acc[4][4] = {};

    float4 xa = *(const float4*)(x + (size_t)(m0 + lm) * DDIM + lk);
    float4 wa = *(const float4*)(A + (size_t)lm * DDIM + lk);
    float4 wb = *(const float4*)(A + (size_t)(lm + 64) * DDIM + lk);

    for (int k0 = 0; k0 < DDIM; k0 += 16) {
        __syncthreads();
        As[lk + 0][lm] = xa.x; As[lk + 1][lm] = xa.y;
        As[lk + 2][lm] = xa.z; As[lk + 3][lm] = xa.w;
        Bs[lk + 0][lm] = wa.x; Bs[lk + 1][lm] = wa.y;
        Bs[lk + 2][lm] = wa.z; Bs[lk + 3][lm] = wa.w;
        Bs[lk + 0][lm + 64] = wb.x; Bs[lk + 1][lm + 64] = wb.y;
        Bs[lk + 2][lm + 64] = wb.z; Bs[lk + 3][lm + 64] = wb.w;
        __syncthreads();
        if (k0 + 16 < DDIM) {
            xa = *(const float4*)(x + (size_t)(m0 + lm) * DDIM + k0 + 16 + lk);
            wa = *(const float4*)(A + (size_t)lm * DDIM + k0 + 16 + lk);
            wb = *(const float4*)(A + (size_t)(lm + 64) * DDIM + k0 + 16 + lk);
        }
#pragma unroll
        for (int k = 0; k < 16; k++) {
            float4 a0 = *(const float4*)&As[k][tm0];
            float4 b0 = *(const float4*)&Bs[k][tn0];
            float4 b1 = *(const float4*)&Bs[k][tn0 + 4];
            u64 bp0 = pack2(b0.x, b0.y), bp1 = pack2(b0.z, b0.w);
            u64 bp2 = pack2(b1.x, b1.y), bp3 = pack2(b1.z, b1.w);
            float av[4] = {a0.x, a0.y, a0.z, a0.w};
#pragma unroll
            for (int i = 0; i < 4; i++) {
                u64 ap = pack2(av[i], av[i]);
                fma2(acc[i][0], ap, bp0); fma2(acc[i][1], ap, bp1);
                fma2(acc[i][2], ap, bp2); fma2(acc[i][3], ap, bp3);
            }
        }
    }
    int e = tn0 >> 4;  // 8 consecutive outputs from a multiple of 8 stay in one expert group
#pragma unroll
    for (int i = 0; i < 4; i++) {
        int t = m0 + tm0 + i;
        float wv = g_w[t * NEXP + e] * SCALING;
        float o[8];
#pragma unroll
        for (int j = 0; j < 4; j++) unpack2(acc[i][j], o[2 * j], o[2 * j + 1]);
#pragma unroll
        for (int j = 0; j < 8; j++) o[j] *= wv;
        float4* dst = (float4*)(g_hw + (size_t)t * ERD + tn0);
        dst[0] = make_float4(o[0], o[1], o[2], o[3]);
        dst[1] = make_float4(o[4], o[5], o[6], o[7]);
    }
}

// ---------------------------------------------------------------------------
// out[t][o] = x@base_W^T + hw@Bcat + bias
// GEMM M=8192, N=4096, K=4096 (+128 lora) ; tile 128x128x16, 256 threads, 8x8
// ---------------------------------------------------------------------------
__global__ __launch_bounds__(256, 2)
void main_kernel(const float* __restrict__ x, const float* __restrict__ W,
                 const float* __restrict__ bias, float* __restrict__ out) {
    __shared__ float As[16][128];
    __shared__ float Bs[16][128];
    int m0 = blockIdx.y * 128;
    int n0 = blockIdx.x * 128;
    int tid = threadIdx.x;
    int lk = (tid & 3) * 4;
    int lm = tid >> 2;        // 0..63
    int tm0 = (tid >> 4) * 8;
    int tn0 = (tid & 15) * 8;
    u64 acc[8][4] = {};

#define COMPUTE_TILE()                                                        \
    _Pragma("unroll")                                                         \
    for (int k = 0; k < 16; k++) {                                            \
        float4 a0 = *(const float4*)&As[k][tm0];                              \
        float4 a1 = *(const float4*)&As[k][tm0 + 4];                          \
        float4 b0 = *(const float4*)&Bs[k][tn0];                              \
        float4 b1 = *(const float4*)&Bs[k][tn0 + 4];                          \
        u64 bp0 = pack2(b0.x, b0.y), bp1 = pack2(b0.z, b0.w);                 \
        u64 bp2 = pack2(b1.x, b1.y), bp3 = pack2(b1.z, b1.w);                 \
        float av[8] = {a0.x, a0.y, a0.z, a0.w, a1.x, a1.y, a1.z, a1.w};       \
        _Pragma("unroll")                                                     \
        for (int i = 0; i < 8; i++) {                                         \
            u64 ap = pack2(av[i], av[i]);                                     \
            fma2(acc[i][0], ap, bp0); fma2(acc[i][1], ap, bp1);               \
            fma2(acc[i][2], ap, bp2); fma2(acc[i][3], ap, bp3);               \
        }                                                                     \
    }

    // ---- phase 1: base GEMM over K=4096 (software-pipelined) ----
    float4 xa = *(const float4*)(x + (size_t)(m0 + lm) * DDIM + lk);
    float4 xb = *(const float4*)(x + (size_t)(m0 + lm + 64) * DDIM + lk);
    float4 wa = *(const float4*)(W + (size_t)(n0 + lm) * DDIM + lk);
    float4 wb = *(const float4*)(W + (size_t)(n0 + lm + 64) * DDIM + lk);
    for (int k0 = 0; k0 < DDIM; k0 += 16) {
        __syncthreads();
        As[lk + 0][lm] = xa.x; As[lk + 1][lm] = xa.y;
        As[lk + 2][lm] = xa.z; As[lk + 3][lm] = xa.w;
        As[lk + 0][lm + 64] = xb.x; As[lk + 1][lm + 64] = xb.y;
        As[lk + 2][lm + 64] = xb.z; As[lk + 3][lm + 64] = xb.w;
        Bs[lk + 0][lm] = wa.x; Bs[lk + 1][lm] = wa.y;
        Bs[lk + 2][lm] = wa.z; Bs[lk + 3][lm] = wa.w;
        Bs[lk + 0][lm + 64] = wb.x; Bs[lk + 1][lm + 64] = wb.y;
        Bs[lk + 2][lm + 64] = wb.z; Bs[lk + 3][lm + 64] = wb.w;
        __syncthreads();
        if (k0 + 16 < DDIM) {
            xa = *(const float4*)(x + (size_t)(m0 + lm) * DDIM + k0 + 16 + lk);
            xb = *(const float4*)(x + (size_t)(m0 + lm + 64) * DDIM + k0 + 16 + lk);
            wa = *(const float4*)(W + (size_t)(n0 + lm) * DDIM + k0 + 16 + lk);
            wb = *(const float4*)(W + (size_t)(n0 + lm + 64) * DDIM + k0 + 16 + lk);
        }
        COMPUTE_TILE();
    }

    // ---- phase 2: lora contraction over K=128, same accumulators ----
    {
        int br = tid >> 5;        // 0..7
        int bc = (tid & 31) * 4;  // 0..124
        float4 ha = *(const float4*)(g_hw + (size_t)(m0 + lm) * ERD + lk);
        float4 hb = *(const float4*)(g_hw + (size_t)(m0 + lm + 64) * ERD + lk);
        float4 b1 = *(const float4*)(g_Bcat + (size_t)br * ODIM + n0 + bc);
        float4 b2 = *(const float4*)(g_Bcat + (size_t)(br + 8) * ODIM + n0 + bc);
        for (int k0 = 0; k0 < ERD; k0 += 16) {
            __syncthreads();
            As[lk + 0][lm] = ha.x; As[lk + 1][lm] = ha.y;
            As[lk + 2][lm] = ha.z; As[lk + 3][lm] = ha.w;
            As[lk + 0][lm + 64] = hb.x; As[lk + 1][lm + 64] = hb.y;
            As[lk + 2][lm + 64] = hb.z; As[lk + 3][lm + 64] = hb.w;
            *(float4*)&Bs[br][bc] = b1;
            *(float4*)&Bs[br + 8][bc] = b2;
            __syncthreads();
            if (k0 + 16 < ERD) {
                ha = *(const float4*)(g_hw + (size_t)(m0 + lm) * ERD + k0 + 16 + lk);
                hb = *(const float4*)(g_hw + (size_t)(m0 + lm + 64) * ERD + k0 + 16 + lk);
                b1 = *(const float4*)(g_Bcat + (size_t)(k0 + 16 + br) * ODIM + n0 + bc);
                b2 = *(const float4*)(g_Bcat + (size_t)(k0 + 16 + br + 8) * ODIM + n0 + bc);
            }
            COMPUTE_TILE();
        }
    }

    // ---- epilogue: + bias, vectorized store ----
    float bv[8];
    {
        float4 t0 = *(const float4*)(bias + n0 + tn0);
        float4 t1 = *(const float4*)(bias + n0 + tn0 + 4);
        bv[0] = t0.x; bv[1] = t0.y; bv[2] = t0.z; bv[3] = t0.w;
        bv[4] = t1.x; bv[5] = t1.y; bv[6] = t1.z; bv[7] = t1.w;
    }
#pragma unroll
    for (int i = 0; i < 8; i++) {
        float o[8];
#pragma unroll
        for (int j = 0; j < 4; j++) unpack2(acc[i][j], o[2 * j], o[2 * j + 1]);
        float4* dst = (float4*)(out + (size_t)(m0 + tm0 + i) * ODIM + n0 + tn0);
        dst[0] = make_float4(o[0] + bv[0], o[1] + bv[1], o[2] + bv[2], o[3] + bv[3]);
        dst[1] = make_float4(o[4] + bv[4], o[5] + bv[5], o[6] + bv[6], o[7] + bv[7]);
    }
#undef COMPUTE_TILE
}

extern "C" void kernel_launch(void* const* d_in, const int* in_sizes, int n_in,
                              void* d_out, int out_size) {
    const float* x    = (const float*)d_in[0];
    const float* bW   = (const float*)d_in[1];
    const float* bb   = (const float*)d_in[2];
    const float* rW   = (const float*)d_in[3];
    const float* rb   = (const float*)d_in[4];
    const float* A    = (const float*)d_in[5];
    const float* Bm   = (const float*)d_in[6];
    const int*   emap = (const int*)d_in[7];
    float* out = (float*)d_out;

    bcat_kernel<<<(ERD * ODIM + 255) / 256, 256>>>(Bm);
    router_kernel<<<MTOK, 128>>>(x, rW, rb, emap);
    hw_kernel<<<MTOK / 64, 256>>>(x, A);
    dim3 grid(ODIM / 128, MTOK / 128);
    main_kernel<<<grid, 256>>>(x, bW, bb, out);
}

// round 4
// speedup vs baseline: 2.1380x; 2.1380x over previous
#include <cuda_runtime.h>
#include <cstdint>

#define MTOK 8192
#define DDIM 4096
#define ODIM 4096
#define NEXP 8
#define RRNK 16
#define ERD  128
#define NLOG 15
#define SCALING 2.0f

// Scratch (allocation-free rule: __device__ globals)
__device__ float g_w[MTOK * NEXP];       // per-token expert combine weights
__device__ float g_hw[MTOK * ERD];       // w-scaled low-rank activations (incl SCALING)
__device__ float g_BcatT[ODIM * ERD];    // B transposed to [o][er]  (K-major)

typedef unsigned long long u64;

__device__ __forceinline__ u64 pack2(float lo, float hi) {
    u64 r; asm("mov.b64 %0, {%1,%2};" : "=l"(r) : "f"(lo), "f"(hi)); return r;
}
__device__ __forceinline__ void unpack2(u64 v, float& lo, float& hi) {
    asm("mov.b64 {%0,%1}, %2;" : "=f"(lo), "=f"(hi) : "l"(v));
}
__device__ __forceinline__ void fma2(u64& d, u64 a, u64 b) {
    asm("fma.rn.f32x2 %0, %1, %2, %0;" : "+l"(d) : "l"(a), "l"(b));
}
__device__ __forceinline__ uint32_t tf32r(float f) {
    uint32_t r; asm("cvt.rna.tf32.f32 %0, %1;" : "=r"(r) : "f"(f)); return r;
}
__device__ __forceinline__ void mma_tf32(float4& d, uint32_t a0, uint32_t a1,
                                         uint32_t a2, uint32_t a3,
                                         uint32_t b0, uint32_t b1) {
    asm("mma.sync.aligned.m16n8k8.row.col.f32.tf32.tf32.f32 "
        "{%0,%1,%2,%3}, {%4,%5,%6,%7}, {%8,%9}, {%0,%1,%2,%3};"
        : "+f"(d.x), "+f"(d.y), "+f"(d.z), "+f"(d.w)
        : "r"(a0), "r"(a1), "r"(a2), "r"(a3), "r"(b0), "r"(b1));
}

// ---------------------------------------------------------------------------
// Router (unchanged, passing)
// ---------------------------------------------------------------------------
__global__ void router_kernel(const float* __restrict__ x,
                              const float* __restrict__ rW,
                              const float* __restrict__ rb,
                              const int* __restrict__ emap) {
    int t = blockIdx.x;
    int tid = threadIdx.x; // 128 threads
    const float4* xr = (const float4*)(x + (size_t)t * DDIM);
    float acc[NLOG];
#pragma unroll
    for (int n = 0; n < NLOG; n++) acc[n] = 0.f;
    for (int d4 = tid; d4 < DDIM / 4; d4 += 128) {
        float4 xv = xr[d4];
#pragma unroll
        for (int n = 0; n < NLOG; n++) {
            float4 wv = ((const float4*)(rW + (size_t)n * DDIM))[d4];
            acc[n] += xv.x * wv.x + xv.y * wv.y + xv.z * wv.z + xv.w * wv.w;
        }
    }
    __shared__ float red[NLOG][128];
#pragma unroll
    for (int n = 0; n < NLOG; n++) red[n][tid] = acc[n];
    __syncthreads();
#pragma unroll
    for (int s = 64; s > 0; s >>= 1) {
        if (tid < s) {
#pragma unroll
            for (int n = 0; n < NLOG; n++) red[n][tid] += red[n][tid + s];
        }
        __syncthreads();
    }
    if (tid == 0) {
        float p[NLOG];
        float mx = -1e30f;
#pragma unroll
        for (int n = 0; n < NLOG; n++) {
            p[n] = red[n][0] + rb[n];
            mx = fmaxf(mx, p[n]);
        }
        float s = 0.f;
#pragma unroll
        for (int n = 0; n < NLOG; n++) { p[n] = expf(p[n] - mx); s += p[n]; }
        float inv = 1.f / s;
#pragma unroll
        for (int n = 0; n < NLOG; n++) p[n] *= inv;
        float wacc[NEXP];
#pragma unroll
        for (int e = 0; e < NEXP; e++) wacc[e] = 0.f;
        bool used[NLOG];
#pragma unroll
        for (int n = 0; n < NLOG; n++) used[n] = false;
        for (int k = 0; k < NEXP; k++) {
            int best = 0; float bv = -1e30f;
            for (int n = 0; n < NLOG; n++)
                if (!used[n] && p[n] > bv) { bv = p[n]; best = n; }
            used[best] = true;
            wacc[emap[best]] += bv;
        }
#pragma unroll
        for (int e = 0; e < NEXP; e++) g_w[t * NEXP + e] = wacc[e];
    }
}

// ---------------------------------------------------------------------------
// BcatT[o][er] = B[e][o][r]
// ---------------------------------------------------------------------------
__global__ void bcat_kernel(const float* __restrict__ Bm) {
    int idx = blockIdx.x * blockDim.x + threadIdx.x;
    if (idx < ODIM * ERD) {
        int o  = idx >> 7;
        int er = idx & 127;
        int e = er >> 4, r = er & 15;
        g_BcatT[idx] = Bm[((size_t)e * ODIM + o) * RRNK + r];
    }
}

// ---------------------------------------------------------------------------
// hw[t][er] = (x[t] . A[e][r]) * w[t][e] * SCALING   (f32x2 SGEMM, unchanged)
// ---------------------------------------------------------------------------
__global__ __launch_bounds__(256, 2)
void hw_kernel(const float* __restrict__ x, const float* __restrict__ A) {
    __shared__ float As[16][64];
    __shared__ float Bs[16][128];
    int m0 = blockIdx.x * 64;
    int tid = threadIdx.x;
    int lk = (tid & 3) * 4;
    int lm = tid >> 2;
    int tm0 = (tid >> 4) * 4;
    int tn0 = (tid & 15) * 8;
    u64 acc[4][4] = {};

    float4 xa = *(const float4*)(x + (size_t)(m0 + lm) * DDIM + lk);
    float4 wa = *(const float4*)(A + (size_t)lm * DDIM + lk);
    float4 wb = *(const float4*)(A + (size_t)(lm + 64) * DDIM + lk);

    for (int k0 = 0; k0 < DDIM; k0 += 16) {
        __syncthreads();
        As[lk + 0][lm] = xa.x; As[lk + 1][lm] = xa.y;
        As[lk + 2][lm] = xa.z; As[lk + 3][lm] = xa.w;
        Bs[lk + 0][lm] = wa.x; Bs[lk + 1][lm] = wa.y;
        Bs[lk + 2][lm] = wa.z; Bs[lk + 3][lm] = wa.w;
        Bs[lk + 0][lm + 64] = wb.x; Bs[lk + 1][lm + 64] = wb.y;
        Bs[lk + 2][lm + 64] = wb.z; Bs[lk + 3][lm + 64] = wb.w;
        __syncthreads();
        if (k0 + 16 < DDIM) {
            xa = *(const float4*)(x + (size_t)(m0 + lm) * DDIM + k0 + 16 + lk);
            wa = *(const float4*)(A + (size_t)lm * DDIM + k0 + 16 + lk);
            wb = *(const float4*)(A + (size_t)(lm + 64) * DDIM + k0 + 16 + lk);
        }
#pragma unroll
        for (int k = 0; k < 16; k++) {
            float4 a0 = *(const float4*)&As[k][tm0];
            float4 b0 = *(const float4*)&Bs[k][tn0];
            float4 b1 = *(const float4*)&Bs[k][tn0 + 4];
            u64 bp0 = pack2(b0.x, b0.y), bp1 = pack2(b0.z, b0.w);
            u64 bp2 = pack2(b1.x, b1.y), bp3 = pack2(b1.z, b1.w);
            float av[4] = {a0.x, a0.y, a0.z, a0.w};
#pragma unroll
            for (int i = 0; i < 4; i++) {
                u64 ap = pack2(av[i], av[i]);
                fma2(acc[i][0], ap, bp0); fma2(acc[i][1], ap, bp1);
                fma2(acc[i][2], ap, bp2); fma2(acc[i][3], ap, bp3);
            }
        }
    }
    int e = tn0 >> 4;
#pragma unroll
    for (int i = 0; i < 4; i++) {
        int t = m0 + tm0 + i;
        float wv = g_w[t * NEXP + e] * SCALING;
        float o[8];
#pragma unroll
        for (int j = 0; j < 4; j++) unpack2(acc[i][j], o[2 * j], o[2 * j + 1]);
#pragma unroll
        for (int j = 0; j < 8; j++) o[j] *= wv;
        float4* dst = (float4*)(g_hw + (size_t)t * ERD + tn0);
        dst[0] = make_float4(o[0], o[1], o[2], o[3]);
        dst[1] = make_float4(o[4], o[5], o[6], o[7]);
    }
}

// ---------------------------------------------------------------------------
// Main GEMM: tf32 mma.sync (base sm_103 ISA — tcgen05 is sm_103a-gated and
// the harness builds .target sm_103).
//   out[m][n] = x@W^T (K=4096) + hw@BcatT^T (K=128) + bias
// CTA 128x128, 8 warps 2x4, warp tile 64x32, K-chunk 32, double-buffered.
//
// smem layout (per matrix, 128 rows): row stride 48 floats (12 x 16B units).
// Element (h, k): c=k&3, P=k>>4, pos=(k>>2)&3 ->
//   word = h*48 + (4P + (c ^ (h&3)))*4 + pos
// This packs a thread's mma fragment (k strided by 4) into ONE 16B unit, and
// the (4h+unit)&7 bank pattern + c^h rotation is conflict-free for both the
// STS.128 fills and the LDS.128 fragment reads (verified 8-distinct banks
// per 8-lane phase).
// ---------------------------------------------------------------------------
#define BM 128
#define BN 128
#define KC 32
#define NCH_BASE (DDIM / KC)             // 128
#define NCHUNK   (NCH_BASE + ERD / KC)   // 132
#define ROWSTRIDE 48                     // floats per smem row (12 units)
#define MAT_FLOATS (128 * ROWSTRIDE)     // 6144
#define STAGE_FLOATS (2 * MAT_FLOATS)    // A + B
#define SMEM_FLOATS (2 * STAGE_FLOATS)   // double buffer: 24576 floats = 96 KB

struct Stage { float4 va[4]; float4 vb[4]; };

__device__ __forceinline__ void ldg_chunk(int i, int m0, int n0, int t,
                                          const float* __restrict__ x,
                                          const float* __restrict__ W,
                                          Stage& s) {
    const float* as; const float* bs; int lda, ldb, k0;
    if (i < NCH_BASE) {
        k0 = i * KC; as = x + k0; lda = DDIM; bs = W + k0; ldb = DDIM;
    } else {
        k0 = (i - NCH_BASE) * KC; as = g_hw + k0; lda = ERD; bs = g_BcatT + k0; ldb = ERD;
    }
    int h = t >> 1, P = t & 1;
    const float* pa = as + (size_t)(m0 + h) * lda + 16 * P;
    const float* pb = bs + (size_t)(n0 + h) * ldb + 16 * P;
#pragma unroll
    for (int j = 0; j < 4; j++) {
        s.va[j] = *(const float4*)(pa + 4 * j);
        s.vb[j] = *(const float4*)(pb + 4 * j);
    }
}

__device__ __forceinline__ void sts_mat(float* sm, int h, int P, int rot,
                                        const float4 v[4]) {
    // unit c content = component c of v[0..3]; store u[jj] at phys unit jj^rot
    uint4 u[4];
    u[0] = make_uint4(tf32r(v[0].x), tf32r(v[1].x), tf32r(v[2].x), tf32r(v[3].x));
    u[1] = make_uint4(tf32r(v[0].y), tf32r(v[1].y), tf32r(v[2].y), tf32r(v[3].y));
    u[2] = make_uint4(tf32r(v[0].z), tf32r(v[1].z), tf32r(v[2].z), tf32r(v[3].z));
    u[3] = make_uint4(tf32r(v[0].w), tf32r(v[1].w), tf32r(v[2].w), tf32r(v[3].w));
    float* base = sm + h * ROWSTRIDE + 16 * P;
#pragma unroll
    for (int jj = 0; jj < 4; jj++)
        *(uint4*)(base + ((jj ^ rot) << 2)) = u[jj];
}

__global__ __launch_bounds__(256, 1)
void main_kernel(const float* __restrict__ x, const float* __restrict__ W,
                 const float* __restrict__ bias, float* __restrict__ out) {
    extern __shared__ float smem[];
    int tid = threadIdx.x;
    int wid = tid >> 5;
    int lane = tid & 31;
    int wm = wid >> 2;          // 0..1 -> rows wm*64
    int wn = wid & 3;           // 0..3 -> cols wn*32
    int c = lane & 3;
    int rq = lane >> 2;
    int m0 = blockIdx.y * BM;
    int n0 = blockIdx.x * BN;
    int h = tid >> 1, P = tid & 1, rot = h & 3;

    float4 acc[4][4];
#pragma unroll
    for (int i = 0; i < 4; i++)
#pragma unroll
        for (int j = 0; j < 4; j++) acc[i][j] = make_float4(0.f, 0.f, 0.f, 0.f);

    // precompute fragment row indices + smem word offsets (invariant per chunk)
    int aoff[4][2], boff[4];
#pragma unroll
    for (int i = 0; i < 4; i++) {
        int rlo = wm * 64 + i * 16 + rq;
        aoff[i][0] = rlo * ROWSTRIDE + ((c ^ (rlo & 3)) << 2);
        aoff[i][1] = (rlo + 8) * ROWSTRIDE + ((c ^ (rlo & 3)) << 2);
    }
#pragma unroll
    for (int j = 0; j < 4; j++) {
        int n = wn * 32 + j * 8 + rq;
        boff[j] = n * ROWSTRIDE + ((c ^ (n & 3)) << 2);
    }

    Stage st;
    ldg_chunk(0, m0, n0, tid, x, W, st);

    for (int i = 0; i < NCHUNK; i++) {
        float* sA = smem + (i & 1) * STAGE_FLOATS;
        float* sB = sA + MAT_FLOATS;
        sts_mat(sA, h, P, rot, st.va);
        sts_mat(sB, h, P, rot, st.vb);
        __syncthreads();
        if (i + 1 < NCHUNK) ldg_chunk(i + 1, m0, n0, tid, x, W, st);

#pragma unroll
        for (int p = 0; p < 2; p++) {
            uint4 af[4][2], bf[4];
#pragma unroll
            for (int ii = 0; ii < 4; ii++) {
                af[ii][0] = *(const uint4*)(sA + aoff[ii][0] + 16 * p);
                af[ii][1] = *(const uint4*)(sA + aoff[ii][1] + 16 * p);
            }
#pragma unroll
            for (int jj = 0; jj < 4; jj++)
                bf[jj] = *(const uint4*)(sB + boff[jj] + 16 * p);
            // kstep 2p: unit positions x (c), y (c+4)
#pragma unroll
            for (int ii = 0; ii < 4; ii++)
#pragma unroll
                for (int jj = 0; jj < 4; jj++)
                    mma_tf32(acc[ii][jj],
                             af[ii][0].x, af[ii][1].x, af[ii][0].y, af[ii][1].y,
                             bf[jj].x, bf[jj].y);
            // kstep 2p+1: positions z, w
#pragma unroll
            for (int ii = 0; ii < 4; ii++)
#pragma unroll
                for (int jj = 0; jj < 4; jj++)
                    mma_tf32(acc[ii][jj],
                             af[ii][0].z, af[ii][1].z, af[ii][0].w, af[ii][1].w,
                             bf[jj].z, bf[jj].w);
        }
    }

    // epilogue: + bias, float2 stores
#pragma unroll
    for (int j = 0; j < 4; j++) {
        int col = n0 + wn * 32 + j * 8 + 2 * c;
        float2 bb = *(const float2*)(bias + col);
#pragma unroll
        for (int i = 0; i < 4; i++) {
            int row = m0 + wm * 64 + i * 16 + rq;
            float2 lo = make_float2(acc[i][j].x + bb.x, acc[i][j].y + bb.y);
            float2 hi = make_float2(acc[i][j].z + bb.x, acc[i][j].w + bb.y);
            *(float2*)(out + (size_t)row * ODIM + col) = lo;
            *(float2*)(out + (size_t)(row + 8) * ODIM + col) = hi;
        }
    }
}

extern "C" void kernel_launch(void* const* d_in, const int* in_sizes, int n_in,
                              void* d_out, int out_size) {
    const float* x    = (const float*)d_in[0];
    const float* bW   = (const float*)d_in[1];
    const float* bb   = (const float*)d_in[2];
    const float* rW   = (const float*)d_in[3];
    const float* rb   = (const float*)d_in[4];
    const float* A    = (const float*)d_in[5];
    const float* Bm   = (const float*)d_in[6];
    const int*   emap = (const int*)d_in[7];
    float* out = (float*)d_out;

    static int configured = 0;
    if (!configured) {
        cudaFuncSetAttribute(main_kernel, cudaFuncAttributeMaxDynamicSharedMemorySize,
                             SMEM_FLOATS * 4);
        configured = 1;
    }

    bcat_kernel<<<(ODIM * ERD + 255) / 256, 256>>>(Bm);
    router_kernel<<<MTOK, 128>>>(x, rW, rb, emap);
    hw_kernel<<<MTOK / 64, 256>>>(x, A);
    dim3 grid(ODIM / BN, MTOK / BM);
    main_kernel<<<grid, 256, SMEM_FLOATS * 4>>>(x, bW, bb, out);
}

// round 5
// speedup vs baseline: 2.9360x; 1.3733x over previous
#include <cuda_runtime.h>
#include <cstdint>

#define MTOK 8192
#define DDIM 4096
#define ODIM 4096
#define NEXP 8
#define RRNK 16
#define ERD  128
#define NLOG 15
#define SCALING 2.0f

// Scratch (allocation-free rule: __device__ globals)
__device__ float g_w[MTOK * NEXP];       // per-token expert combine weights
__device__ float g_hw[MTOK * ERD];       // w-scaled low-rank acts (tf32-rounded)
__device__ float g_BcatT[ODIM * ERD];    // B transposed [o][er] (tf32-rounded)
__device__ float g_xr[MTOK * DDIM];      // x pre-rounded to tf32
__device__ float g_wr[ODIM * DDIM];      // base_W pre-rounded to tf32

typedef unsigned long long u64;

__device__ __forceinline__ u64 pack2(float lo, float hi) {
    u64 r; asm("mov.b64 %0, {%1,%2};" : "=l"(r) : "f"(lo), "f"(hi)); return r;
}
__device__ __forceinline__ void unpack2(u64 v, float& lo, float& hi) {
    asm("mov.b64 {%0,%1}, %2;" : "=f"(lo), "=f"(hi) : "l"(v));
}
__device__ __forceinline__ void fma2(u64& d, u64 a, u64 b) {
    asm("fma.rn.f32x2 %0, %1, %2, %0;" : "+l"(d) : "l"(a), "l"(b));
}
__device__ __forceinline__ uint32_t tf32r(float f) {
    uint32_t r; asm("cvt.rna.tf32.f32 %0, %1;" : "=r"(r) : "f"(f)); return r;
}
__device__ __forceinline__ uint32_t smem_u32(const void* p) {
    uint32_t a;
    asm("{ .reg .u64 t; cvta.to.shared.u64 t, %1; cvt.u32.u64 %0, t; }" : "=r"(a) : "l"(p));
    return a;
}
__device__ __forceinline__ void cpasync16(uint32_t saddr, const void* g) {
    asm volatile("cp.async.cg.shared.global [%0], [%1], 16;" :: "r"(saddr), "l"(g));
}
__device__ __forceinline__ void mma_tf32(float* d, uint32_t a0, uint32_t a1,
                                         uint32_t a2, uint32_t a3,
                                         uint32_t b0, uint32_t b1) {
    asm("mma.sync.aligned.m16n8k8.row.col.f32.tf32.tf32.f32 "
        "{%0,%1,%2,%3}, {%4,%5,%6,%7}, {%8,%9}, {%0,%1,%2,%3};"
        : "+f"(d[0]), "+f"(d[1]), "+f"(d[2]), "+f"(d[3])
        : "r"(a0), "r"(a1), "r"(a2), "r"(a3), "r"(b0), "r"(b1));
}

// ---------------------------------------------------------------------------
// Pre-round x / W to tf32 (removes all cvt from the GEMM mainloop and makes
// the data cp.async-able as raw bits)
// ---------------------------------------------------------------------------
__global__ void round_x_kernel(const float* __restrict__ src) {
    int i = blockIdx.x * blockDim.x + threadIdx.x;
    float4 v = ((const float4*)src)[i];
    ((uint4*)g_xr)[i] = make_uint4(tf32r(v.x), tf32r(v.y), tf32r(v.z), tf32r(v.w));
}
__global__ void round_w_kernel(const float* __restrict__ src) {
    int i = blockIdx.x * blockDim.x + threadIdx.x;
    float4 v = ((const float4*)src)[i];
    ((uint4*)g_wr)[i] = make_uint4(tf32r(v.x), tf32r(v.y), tf32r(v.z), tf32r(v.w));
}

// ---------------------------------------------------------------------------
// Router (unchanged, passing)
// ---------------------------------------------------------------------------
__global__ void router_kernel(const float* __restrict__ x,
                              const float* __restrict__ rW,
                              const float* __restrict__ rb,
                              const int* __restrict__ emap) {
    int t = blockIdx.x;
    int tid = threadIdx.x;
    const float4* xr = (const float4*)(x + (size_t)t * DDIM);
    float acc[NLOG];
#pragma unroll
    for (int n = 0; n < NLOG; n++) acc[n] = 0.f;
    for (int d4 = tid; d4 < DDIM / 4; d4 += 128) {
        float4 xv = xr[d4];
#pragma unroll
        for (int n = 0; n < NLOG; n++) {
            float4 wv = ((const float4*)(rW + (size_t)n * DDIM))[d4];
            acc[n] += xv.x * wv.x + xv.y * wv.y + xv.z * wv.z + xv.w * wv.w;
        }
    }
    __shared__ float red[NLOG][128];
#pragma unroll
    for (int n = 0; n < NLOG; n++) red[n][tid] = acc[n];
    __syncthreads();
#pragma unroll
    for (int s = 64; s > 0; s >>= 1) {
        if (tid < s) {
#pragma unroll
            for (int n = 0; n < NLOG; n++) red[n][tid] += red[n][tid + s];
        }
        __syncthreads();
    }
    if (tid == 0) {
        float p[NLOG];
        float mx = -1e30f;
#pragma unroll
        for (int n = 0; n < NLOG; n++) {
            p[n] = red[n][0] + rb[n];
            mx = fmaxf(mx, p[n]);
        }
        float s = 0.f;
#pragma unroll
        for (int n = 0; n < NLOG; n++) { p[n] = expf(p[n] - mx); s += p[n]; }
        float inv = 1.f / s;
#pragma unroll
        for (int n = 0; n < NLOG; n++) p[n] *= inv;
        float wacc[NEXP];
#pragma unroll
        for (int e = 0; e < NEXP; e++) wacc[e] = 0.f;
        bool used[NLOG];
#pragma unroll
        for (int n = 0; n < NLOG; n++) used[n] = false;
        for (int k = 0; k < NEXP; k++) {
            int best = 0; float bv = -1e30f;
            for (int n = 0; n < NLOG; n++)
                if (!used[n] && p[n] > bv) { bv = p[n]; best = n; }
            used[best] = true;
            wacc[emap[best]] += bv;
        }
#pragma unroll
        for (int e = 0; e < NEXP; e++) g_w[t * NEXP + e] = wacc[e];
    }
}

// ---------------------------------------------------------------------------
// BcatT[o][er] = B[e][o][r]   (tf32-rounded at write)
// ---------------------------------------------------------------------------
__global__ void bcat_kernel(const float* __restrict__ Bm) {
    int idx = blockIdx.x * blockDim.x + threadIdx.x;
    if (idx < ODIM * ERD) {
        int o  = idx >> 7;
        int er = idx & 127;
        int e = er >> 4, r = er & 15;
        ((uint32_t*)g_BcatT)[idx] = tf32r(Bm[((size_t)e * ODIM + o) * RRNK + r]);
    }
}

// ---------------------------------------------------------------------------
// hw[t][er] = (x[t] . A[e][r]) * w[t][e] * SCALING  (f32x2 SGEMM; tf32 at write)
// ---------------------------------------------------------------------------
__global__ __launch_bounds__(256, 2)
void hw_kernel(const float* __restrict__ x, const float* __restrict__ A) {
    __shared__ float As[16][64];
    __shared__ float Bs[16][128];
    int m0 = blockIdx.x * 64;
    int tid = threadIdx.x;
    int lk = (tid & 3) * 4;
    int lm = tid >> 2;
    int tm0 = (tid >> 4) * 4;
    int tn0 = (tid & 15) * 8;
    u64 acc[4][4] = {};

    float4 xa = *(const float4*)(x + (size_t)(m0 + lm) * DDIM + lk);
    float4 wa = *(const float4*)(A + (size_t)lm * DDIM + lk);
    float4 wb = *(const float4*)(A + (size_t)(lm + 64) * DDIM + lk);

    for (int k0 = 0; k0 < DDIM; k0 += 16) {
        __syncthreads();
        As[lk + 0][lm] = xa.x; As[lk + 1][lm] = xa.y;
        As[lk + 2][lm] = xa.z; As[lk + 3][lm] = xa.w;
        Bs[lk + 0][lm] = wa.x; Bs[lk + 1][lm] = wa.y;
        Bs[lk + 2][lm] = wa.z; Bs[lk + 3][lm] = wa.w;
        Bs[lk + 0][lm + 64] = wb.x; Bs[lk + 1][lm + 64] = wb.y;
        Bs[lk + 2][lm + 64] = wb.z; Bs[lk + 3][lm + 64] = wb.w;
        __syncthreads();
        if (k0 + 16 < DDIM) {
            xa = *(const float4*)(x + (size_t)(m0 + lm) * DDIM + k0 + 16 + lk);
            wa = *(const float4*)(A + (size_t)lm * DDIM + k0 + 16 + lk);
            wb = *(const float4*)(A + (size_t)(lm + 64) * DDIM + k0 + 16 + lk);
        }
#pragma unroll
        for (int k = 0; k < 16; k++) {
            float4 a0 = *(const float4*)&As[k][tm0];
            float4 b0 = *(const float4*)&Bs[k][tn0];
            float4 b1 = *(const float4*)&Bs[k][tn0 + 4];
            u64 bp0 = pack2(b0.x, b0.y), bp1 = pack2(b0.z, b0.w);
            u64 bp2 = pack2(b1.x, b1.y), bp3 = pack2(b1.z, b1.w);
            float av[4] = {a0.x, a0.y, a0.z, a0.w};
#pragma unroll
            for (int i = 0; i < 4; i++) {
                u64 ap = pack2(av[i], av[i]);
                fma2(acc[i][0], ap, bp0); fma2(acc[i][1], ap, bp1);
                fma2(acc[i][2], ap, bp2); fma2(acc[i][3], ap, bp3);
            }
        }
    }
    int e = tn0 >> 4;
#pragma unroll
    for (int i = 0; i < 4; i++) {
        int t = m0 + tm0 + i;
        float wv = g_w[t * NEXP + e] * SCALING;
        float o[8];
#pragma unroll
        for (int j = 0; j < 4; j++) unpack2(acc[i][j], o[2 * j], o[2 * j + 1]);
        uint32_t* dst = (uint32_t*)(g_hw + (size_t)t * ERD + tn0);
#pragma unroll
        for (int j = 0; j < 8; j++) dst[j] = tf32r(o[j] * wv);
    }
}

// ---------------------------------------------------------------------------
// Main GEMM: tf32 mma.sync, cp.async 3-stage pipeline, pre-rounded inputs.
//   out = x@W^T (K=4096) + hw@BcatT^T (K=128) + bias
// CTA 128x256, 8 warps (2x4), warp tile 64x64, K-chunk 32.
// smem: 128B rows (32 floats), unit u (16B) at phys u^(row&7)  (SW128 XOR).
// k-permutation: unit u holds phys k {4u..4u+3}; mma #0 of a 16-k half uses
// components (x,y) = phys k (4c, 4c+1), mma #1 uses (z,w). A and B use the
// same permutation, so the sum over k is exact.
// ---------------------------------------------------------------------------
#define BM 128
#define BN 256
#define KC 32
#define NCH_BASE (DDIM / KC)             // 128
#define NCHUNK   (NCH_BASE + ERD / KC)   // 132
#define NSTAGE 3
#define A_BYTES (BM * KC * 4)            // 16384
#define B_BYTES (BN * KC * 4)            // 32768
#define STG_BYTES (A_BYTES + B_BYTES)    // 49152
#define SMEM_BYTES (NSTAGE * STG_BYTES)  // 147456

__device__ __forceinline__ void issue_chunk(int i, int stg, int m0, int n0,
                                            int tid, uint32_t smem_base) {
    const float* as; const float* bs; int lda, ldb;
    if (i < NCH_BASE) {
        int k0 = i * KC; as = g_xr + k0; lda = DDIM; bs = g_wr + k0; ldb = DDIM;
    } else {
        int k0 = (i - NCH_BASE) * KC; as = g_hw + k0; lda = ERD; bs = g_BcatT + k0; ldb = ERD;
    }
    uint32_t sa = smem_base + stg * STG_BYTES;
    uint32_t sb = sa + A_BYTES;
#pragma unroll
    for (int j = 0; j < 4; j++) {
        int g = tid + j * 256, row = g >> 3, u = g & 7;
        cpasync16(sa + row * 128 + ((u ^ (row & 7)) << 4),
                  as + (size_t)(m0 + row) * lda + u * 4);
    }
#pragma unroll
    for (int j = 0; j < 8; j++) {
        int g = tid + j * 256, row = g >> 3, u = g & 7;
        cpasync16(sb + row * 128 + ((u ^ (row & 7)) << 4),
                  bs + (size_t)(n0 + row) * ldb + u * 4);
    }
}

__global__ __launch_bounds__(256, 1)
void main_kernel(const float* __restrict__ bias, float* __restrict__ out) {
    extern __shared__ char smem[];
    uint32_t smem_base = smem_u32(smem);
    int tid = threadIdx.x;
    int wid = tid >> 5;
    int lane = tid & 31;
    int wm = wid >> 2;          // 0..1 -> rows wm*64
    int wn = wid & 3;           // 0..3 -> cols wn*64
    int c = lane & 3;
    int rq = lane >> 2;
    int m0 = blockIdx.y * BM;
    int n0 = blockIdx.x * BN;

    float acc[4][8][4];
#pragma unroll
    for (int i = 0; i < 4; i++)
#pragma unroll
        for (int j = 0; j < 8; j++)
#pragma unroll
            for (int q = 0; q < 4; q++) acc[i][j][q] = 0.f;

    // fragment smem byte offsets for p=0 (p=1 = offset ^ 64)
    int aoff[4][2], boff[8];
#pragma unroll
    for (int i = 0; i < 4; i++) {
        int r0 = wm * 64 + i * 16 + rq;
        int r1 = r0 + 8;
        aoff[i][0] = r0 * 128 + ((c ^ (r0 & 7)) << 4);
        aoff[i][1] = r1 * 128 + ((c ^ (r1 & 7)) << 4);
    }
#pragma unroll
    for (int j = 0; j < 8; j++) {
        int n = wn * 64 + j * 8 + rq;
        boff[j] = n * 128 + ((c ^ (n & 7)) << 4);
    }

    issue_chunk(0, 0, m0, n0, tid, smem_base);
    asm volatile("cp.async.commit_group;" ::: "memory");
    issue_chunk(1, 1, m0, n0, tid, smem_base);
    asm volatile("cp.async.commit_group;" ::: "memory");

    for (int i = 0; i < NCHUNK; i++) {
        asm volatile("cp.async.wait_group 1;" ::: "memory");
        __syncthreads();
        if (i + 2 < NCHUNK)
            issue_chunk(i + 2, (i + 2) % NSTAGE, m0, n0, tid, smem_base);
        asm volatile("cp.async.commit_group;" ::: "memory");

        const char* sa = smem + (i % NSTAGE) * STG_BYTES;
        const char* sb = sa + A_BYTES;
#pragma unroll
        for (int p = 0; p < 2; p++) {
            uint4 af[4][2], bf[8];
#pragma unroll
            for (int ii = 0; ii < 4; ii++) {
                af[ii][0] = *(const uint4*)(sa + (aoff[ii][0] ^ (p << 6)));
                af[ii][1] = *(const uint4*)(sa + (aoff[ii][1] ^ (p << 6)));
            }
#pragma unroll
            for (int jj = 0; jj < 8; jj++)
                bf[jj] = *(const uint4*)(sb + (boff[jj] ^ (p << 6)));
#pragma unroll
            for (int ii = 0; ii < 4; ii++)
#pragma unroll
                for (int jj = 0; jj < 8; jj++) {
                    mma_tf32(acc[ii][jj],
                             af[ii][0].x, af[ii][1].x, af[ii][0].y, af[ii][1].y,
                             bf[jj].x, bf[jj].y);
                    mma_tf32(acc[ii][jj],
                             af[ii][0].z, af[ii][1].z, af[ii][0].w, af[ii][1].w,
                             bf[jj].z, bf[jj].w);
                }
        }
    }

    // epilogue: + bias, float2 stores
#pragma unroll
    for (int j = 0; j < 8; j++) {
        int col = n0 + wn * 64 + j * 8 + 2 * c;
        float2 bb = *(const float2*)(bias + col);
#pragma unroll
        for (int i = 0; i < 4; i++) {
            int row = m0 + wm * 64 + i * 16 + rq;
            float2 lo = make_float2(acc[i][j][0] + bb.x, acc[i][j][1] + bb.y);
            float2 hi = make_float2(acc[i][j][2] + bb.x, acc[i][j][3] + bb.y);
            *(float2*)(out + (size_t)row * ODIM + col) = lo;
            *(float2*)(out + (size_t)(row + 8) * ODIM + col) = hi;
        }
    }
}

extern "C" void kernel_launch(void* const* d_in, const int* in_sizes, int n_in,
                              void* d_out, int out_size) {
    const float* x    = (const float*)d_in[0];
    const float* bW   = (const float*)d_in[1];
    const float* bb   = (const float*)d_in[2];
    const float* rW   = (const float*)d_in[3];
    const float* rb   = (const float*)d_in[4];
    const float* A    = (const float*)d_in[5];
    const float* Bm   = (const float*)d_in[6];
    const int*   emap = (const int*)d_in[7];
    float* out = (float*)d_out;

    static int configured = 0;
    if (!configured) {
        cudaFuncSetAttribute(main_kernel, cudaFuncAttributeMaxDynamicSharedMemorySize,
                             SMEM_BYTES);
        configured = 1;
    }

    round_x_kernel<<<(MTOK * DDIM / 4) / 256, 256>>>(x);
    round_w_kernel<<<(ODIM * DDIM / 4) / 256, 256>>>(bW);
    bcat_kernel<<<(ODIM * ERD + 255) / 256, 256>>>(Bm);
    router_kernel<<<MTOK, 128>>>(x, rW, rb, emap);
    hw_kernel<<<MTOK / 64, 256>>>(x, A);
    dim3 grid(ODIM / BN, MTOK / BM);
    main_kernel<<<grid, 256, SMEM_BYTES>>>(bb, out);
}

// round 7
// speedup vs baseline: 3.3559x; 1.1430x over previous
#include <cuda_runtime.h>
#include <cstdint>

#define MTOK 8192
#define DDIM 4096
#define ODIM 4096
#define NEXP 8
#define RRNK 16
#define ERD  128
#define NLOG 15
#define SCALING 2.0f

// Scratch (allocation-free rule: __device__ globals)
__device__ float g_w[MTOK * NEXP];       // per-token expert combine weights
__device__ float g_hw[MTOK * ERD];       // w-scaled low-rank acts (tf32-rounded)
__device__ float g_BcatT[ODIM * ERD];    // B transposed [o][er] (tf32-rounded)
__device__ float g_xr[MTOK * DDIM];      // x pre-rounded to tf32
__device__ float g_wr[ODIM * DDIM];      // base_W pre-rounded to tf32
__device__ float g_ar[ERD * DDIM];       // A_flat tf32
__device__ float g_h[MTOK * 192];        // cols 0..127: h (tf32 GEMM), 128..142: fp32 logits

typedef unsigned long long u64;

__device__ __forceinline__ u64 pack2(float lo, float hi) {
    u64 r; asm("mov.b64 %0, {%1,%2};" : "=l"(r) : "f"(lo), "f"(hi)); return r;
}
__device__ __forceinline__ void unpack2(u64 v, float& lo, float& hi) {
    asm("mov.b64 {%0,%1}, %2;" : "=f"(lo), "=f"(hi) : "l"(v));
}
__device__ __forceinline__ void fma2(u64& d, u64 a, u64 b) {
    asm("fma.rn.f32x2 %0, %1, %2, %0;" : "+l"(d) : "l"(a), "l"(b));
}
__device__ __forceinline__ uint32_t tf32r(float f) {
    uint32_t r; asm("cvt.rna.tf32.f32 %0, %1;" : "=r"(r) : "f"(f)); return r;
}
__device__ __forceinline__ uint32_t smem_u32(const void* p) {
    uint32_t a;
    asm("{ .reg .u64 t; cvta.to.shared.u64 t, %1; cvt.u32.u64 %0, t; }" : "=r"(a) : "l"(p));
    return a;
}
__device__ __forceinline__ void cpasync16(uint32_t saddr, const void* g) {
    asm volatile("cp.async.cg.shared.global [%0], [%1], 16;" :: "r"(saddr), "l"(g));
}
__device__ __forceinline__ void mma_tf32(float* d, uint32_t a0, uint32_t a1,
                                         uint32_t a2, uint32_t a3,
                                         uint32_t b0, uint32_t b1) {
    asm("mma.sync.aligned.m16n8k8.row.col.f32.tf32.tf32.f32 "
        "{%0,%1,%2,%3}, {%4,%5,%6,%7}, {%8,%9}, {%0,%1,%2,%3};"
        : "+f"(d[0]), "+f"(d[1]), "+f"(d[2]), "+f"(d[3])
        : "r"(a0), "r"(a1), "r"(a2), "r"(a3), "r"(b0), "r"(b1));
}

// ---------------------------------------------------------------------------
// Pre-rounding kernels
// ---------------------------------------------------------------------------
__global__ void round_x_kernel(const float* __restrict__ src) {
    int i = blockIdx.x * blockDim.x + threadIdx.x;
    float4 v = ((const float4*)src)[i];
    ((uint4*)g_xr)[i] = make_uint4(tf32r(v.x), tf32r(v.y), tf32r(v.z), tf32r(v.w));
}
__global__ void round_w_kernel(const float* __restrict__ src) {
    int i = blockIdx.x * blockDim.x + threadIdx.x;
    float4 v = ((const float4*)src)[i];
    ((uint4*)g_wr)[i] = make_uint4(tf32r(v.x), tf32r(v.y), tf32r(v.z), tf32r(v.w));
}
__global__ void ar_fill_kernel(const float* __restrict__ A) {
    int i = blockIdx.x * blockDim.x + threadIdx.x;   // over ERD*DDIM/4
    float4 v = ((const float4*)A)[i];
    ((uint4*)g_ar)[i] = make_uint4(tf32r(v.x), tf32r(v.y), tf32r(v.z), tf32r(v.w));
}
// BcatT[o][er] = B[e][o][r]
__global__ void bcat_kernel(const float* __restrict__ Bm) {
    int idx = blockIdx.x * blockDim.x + threadIdx.x;
    if (idx < ODIM * ERD) {
        int o  = idx >> 7;
        int er = idx & 127;
        int e = er >> 4, r = er & 15;
        ((uint32_t*)g_BcatT)[idx] = tf32r(Bm[((size_t)e * ODIM + o) * RRNK + r]);
    }
}

// ---------------------------------------------------------------------------
// Exact fp32 router logits (routing decisions must match fp32 reference).
// 128 blocks x 64 tokens: rW L2 traffic = 128 * 240KB = 30MB (vs R5's 2GB).
// 4 threads per token cover k-quarters; f32x2 accumulators.
// ---------------------------------------------------------------------------
__global__ __launch_bounds__(256, 1)
void logits_kernel(const float* __restrict__ x, const float* __restrict__ rW) {
    int tid = threadIdx.x;
    int tok = blockIdx.x * 64 + (tid >> 2);
    int part = tid & 3;
    u64 acc[NLOG];
#pragma unroll
    for (int n = 0; n < NLOG; n++) acc[n] = 0;
    const float4* xr = (const float4*)(x + (size_t)tok * DDIM);
    for (int k4 = part; k4 < DDIM / 4; k4 += 4) {
        float4 xv = xr[k4];
        u64 xp0 = pack2(xv.x, xv.y), xp1 = pack2(xv.z, xv.w);
#pragma unroll
        for (int n = 0; n < NLOG; n++) {
            float4 wv = ((const float4*)(rW + (size_t)n * DDIM))[k4];
            fma2(acc[n], xp0, pack2(wv.x, wv.y));
            fma2(acc[n], xp1, pack2(wv.z, wv.w));
        }
    }
    __shared__ float red[4][64][NLOG + 1];
#pragma unroll
    for (int n = 0; n < NLOG; n++) {
        float lo, hi; unpack2(acc[n], lo, hi);
        red[part][tid >> 2][n] = lo + hi;
    }
    __syncthreads();
    if (part == 0) {
        int tl = tid >> 2;
#pragma unroll
        for (int n = 0; n < NLOG; n++)
            g_h[(size_t)tok * 192 + ERD + n] =
                red[0][tl][n] + red[1][tl][n] + red[2][tl][n] + red[3][tl][n];
    }
}

// ---------------------------------------------------------------------------
// h GEMM (tf32 mma):  g_h[:, 0:128] = g_xr @ g_ar^T
// CTA 64x128, 8 warps (2x4), warp tile 32x32, K-chunk 32, 3-stage cp.async.
// ---------------------------------------------------------------------------
#define BMH 64
#define BNH 128
#define AH_BYTES (BMH * 32 * 4)           // 8192
#define BH_BYTES (BNH * 32 * 4)           // 16384
#define STGH_BYTES (AH_BYTES + BH_BYTES)  // 24576
#define SMEMH_BYTES (3 * STGH_BYTES)      // 73728

__device__ __forceinline__ void hwr_issue(int i, int stg, int m0, int tid,
                                          uint32_t smem_base) {
    int k0 = i * 32;
    uint32_t sa = smem_base + stg * STGH_BYTES;
    uint32_t sb = sa + AH_BYTES;
#pragma unroll
    for (int j = 0; j < 2; j++) {
        int g = tid + j * 256, row = g >> 3, u = g & 7;
        cpasync16(sa + row * 128 + ((u ^ (row & 7)) << 4),
                  g_xr + (size_t)(m0 + row) * DDIM + k0 + u * 4);
    }
#pragma unroll
    for (int j = 0; j < 4; j++) {
        int g = tid + j * 256, row = g >> 3, u = g & 7;
        cpasync16(sb + row * 128 + ((u ^ (row & 7)) << 4),
                  g_ar + (size_t)row * DDIM + k0 + u * 4);
    }
}

__global__ __launch_bounds__(256, 1)
void hwr_kernel() {
    extern __shared__ char smem[];
    uint32_t smem_base = smem_u32(smem);
    int tid = threadIdx.x;
    int wid = tid >> 5;
    int lane = tid & 31;
    int wm = wid >> 2;          // 0..1 -> rows wm*32
    int wn = wid & 3;           // 0..3 -> cols wn*32
    int c = lane & 3;
    int rq = lane >> 2;
    int m0 = blockIdx.x * BMH;

    float acc[2][4][4];
#pragma unroll
    for (int i = 0; i < 2; i++)
#pragma unroll
        for (int j = 0; j < 4; j++)
#pragma unroll
            for (int q = 0; q < 4; q++) acc[i][j][q] = 0.f;

    int aoff[2][2], boff[4];
#pragma unroll
    for (int i = 0; i < 2; i++) {
        int r0 = wm * 32 + i * 16 + rq, r1 = r0 + 8;
        aoff[i][0] = r0 * 128 + ((c ^ (r0 & 7)) << 4);
        aoff[i][1] = r1 * 128 + ((c ^ (r1 & 7)) << 4);
    }
#pragma unroll
    for (int j = 0; j < 4; j++) {
        int n = wn * 32 + j * 8 + rq;
        boff[j] = n * 128 + ((c ^ (n & 7)) << 4);
    }

    hwr_issue(0, 0, m0, tid, smem_base);
    asm volatile("cp.async.commit_group;" ::: "memory");
    hwr_issue(1, 1, m0, tid, smem_base);
    asm volatile("cp.async.commit_group;" ::: "memory");

    const int NCH = DDIM / 32;  // 128
    for (int i = 0; i < NCH; i++) {
        asm volatile("cp.async.wait_group 1;" ::: "memory");
        __syncthreads();
        if (i + 2 < NCH) hwr_issue(i + 2, (i + 2) % 3, m0, tid, smem_base);
        asm volatile("cp.async.commit_group;" ::: "memory");

        const char* sa = smem + (i % 3) * STGH_BYTES;
        const char* sb = sa + AH_BYTES;
#pragma unroll
        for (int p = 0; p < 2; p++) {
            uint4 af[2][2], bf[4];
#pragma unroll
            for (int ii = 0; ii < 2; ii++) {
                af[ii][0] = *(const uint4*)(sa + (aoff[ii][0] ^ (p << 6)));
                af[ii][1] = *(const uint4*)(sa + (aoff[ii][1] ^ (p << 6)));
            }
#pragma unroll
            for (int jj = 0; jj < 4; jj++)
                bf[jj] = *(const uint4*)(sb + (boff[jj] ^ (p << 6)));
#pragma unroll
            for (int ii = 0; ii < 2; ii++)
#pragma unroll
                for (int jj = 0; jj < 4; jj++) {
                    mma_tf32(acc[ii][jj],
                             af[ii][0].x, af[ii][1].x, af[ii][0].y, af[ii][1].y,
                             bf[jj].x, bf[jj].y);
                    mma_tf32(acc[ii][jj],
                             af[ii][0].z, af[ii][1].z, af[ii][0].w, af[ii][1].w,
                             bf[jj].z, bf[jj].w);
                }
        }
    }

#pragma unroll
    for (int j = 0; j < 4; j++) {
        int col = wn * 32 + j * 8 + 2 * c;
#pragma unroll
        for (int i = 0; i < 2; i++) {
            int row = m0 + wm * 32 + i * 16 + rq;
            *(float2*)(g_h + (size_t)row * 192 + col) =
                make_float2(acc[i][j][0], acc[i][j][1]);
            *(float2*)(g_h + (size_t)(row + 8) * 192 + col) =
                make_float2(acc[i][j][2], acc[i][j][3]);
        }
    }
}

// ---------------------------------------------------------------------------
// w_kernel: per token, softmax over 15 fp32 logits, top-8, combine weights
// ---------------------------------------------------------------------------
__global__ void w_kernel(const float* __restrict__ rb,
                         const int* __restrict__ emap) {
    int t = blockIdx.x * blockDim.x + threadIdx.x;
    if (t >= MTOK) return;
    float p[NLOG];
    float mx = -1e30f;
#pragma unroll
    for (int n = 0; n < NLOG; n++) {
        p[n] = g_h[(size_t)t * 192 + ERD + n] + rb[n];
        mx = fmaxf(mx, p[n]);
    }
    float s = 0.f;
#pragma unroll
    for (int n = 0; n < NLOG; n++) { p[n] = expf(p[n] - mx); s += p[n]; }
    float inv = 1.f / s;
#pragma unroll
    for (int n = 0; n < NLOG; n++) p[n] *= inv;
    float wacc[NEXP];
#pragma unroll
    for (int e = 0; e < NEXP; e++) wacc[e] = 0.f;
    bool used[NLOG];
#pragma unroll
    for (int n = 0; n < NLOG; n++) used[n] = false;
    for (int k = 0; k < NEXP; k++) {       // strict > = lowest index on ties
        int best = 0; float bv = -1e30f;
        for (int n = 0; n < NLOG; n++)
            if (!used[n] && p[n] > bv) { bv = p[n]; best = n; }
        used[best] = true;
        wacc[emap[best]] += bv;
    }
#pragma unroll
    for (int e = 0; e < NEXP; e++) g_w[t * NEXP + e] = wacc[e];
}

// ---------------------------------------------------------------------------
// scale_kernel: g_hw[t][er] = tf32( h[t][er] * w[t][er/16] * SCALING )
// ---------------------------------------------------------------------------
__global__ void scale_kernel() {
    int idx = blockIdx.x * blockDim.x + threadIdx.x;  // over MTOK*ERD/4
    int t = idx >> 5;
    int er4 = (idx & 31) * 4;
    float wv = g_w[t * NEXP + (er4 >> 4)] * SCALING;
    const float* h = g_h + (size_t)t * 192 + er4;
    ((uint4*)(g_hw + (size_t)t * ERD + er4))[0] =
        make_uint4(tf32r(h[0] * wv), tf32r(h[1] * wv),
                   tf32r(h[2] * wv), tf32r(h[3] * wv));
}

// ---------------------------------------------------------------------------
// Main GEMM: tf32 mma.sync, 4-stage cp.async pipeline, pre-rounded inputs.
//   out = x@W^T (K=4096) + hw@BcatT^T (K=128) + bias
// CTA 128x256, 8 warps (2x4), warp tile 64x64, K-chunk 32.
// ---------------------------------------------------------------------------
#define BM 128
#define BN 256
#define KC 32
#define NCH_BASE (DDIM / KC)             // 128
#define NCHUNK   (NCH_BASE + ERD / KC)   // 132
#define NSTAGE 4
#define A_BYTES (BM * KC * 4)            // 16384
#define B_BYTES (BN * KC * 4)            // 32768
#define STG_BYTES (A_BYTES + B_BYTES)    // 49152
#define SMEM_BYTES (NSTAGE * STG_BYTES)  // 196608

__device__ __forceinline__ void issue_chunk(int i, int stg, int m0, int n0,
                                            int tid, uint32_t smem_base) {
    const float* as; const float* bs; int lda, ldb;
    if (i < NCH_BASE) {
        int k0 = i * KC; as = g_xr + k0; lda = DDIM; bs = g_wr + k0; ldb = DDIM;
    } else {
        int k0 = (i - NCH_BASE) * KC; as = g_hw + k0; lda = ERD; bs = g_BcatT + k0; ldb = ERD;
    }
    uint32_t sa = smem_base + stg * STG_BYTES;
    uint32_t sb = sa + A_BYTES;
#pragma unroll
    for (int j = 0; j < 4; j++) {
        int g = tid + j * 256, row = g >> 3, u = g & 7;
        cpasync16(sa + row * 128 + ((u ^ (row & 7)) << 4),
                  as + (size_t)(m0 + row) * lda + u * 4);
    }
#pragma unroll
    for (int j = 0; j < 8; j++) {
        int g = tid + j * 256, row = g >> 3, u = g & 7;
        cpasync16(sb + row * 128 + ((u ^ (row & 7)) << 4),
                  bs + (size_t)(n0 + row) * ldb + u * 4);
    }
}

__global__ __launch_bounds__(256, 1)
void main_kernel(const float* __restrict__ bias, float* __restrict__ out) {
    extern __shared__ char smem[];
    uint32_t smem_base = smem_u32(smem);
    int tid = threadIdx.x;
    int wid = tid >> 5;
    int lane = tid & 31;
    int wm = wid >> 2;          // 0..1 -> rows wm*64
    int wn = wid & 3;           // 0..3 -> cols wn*64
    int c = lane & 3;
    int rq = lane >> 2;
    int m0 = blockIdx.y * BM;
    int n0 = blockIdx.x * BN;

    float acc[4][8][4];
#pragma unroll
    for (int i = 0; i < 4; i++)
#pragma unroll
        for (int j = 0; j < 8; j++)
#pragma unroll
            for (int q = 0; q < 4; q++) acc[i][j][q] = 0.f;

    int aoff[4][2], boff[8];
#pragma unroll
    for (int i = 0; i < 4; i++) {
        int r0 = wm * 64 + i * 16 + rq, r1 = r0 + 8;
        aoff[i][0] = r0 * 128 + ((c ^ (r0 & 7)) << 4);
        aoff[i][1] = r1 * 128 + ((c ^ (r1 & 7)) << 4);
    }
#pragma unroll
    for (int j = 0; j < 8; j++) {
        int n = wn * 64 + j * 8 + rq;
        boff[j] = n * 128 + ((c ^ (n & 7)) << 4);
    }

#pragma unroll
    for (int s = 0; s < NSTAGE - 1; s++) {
        issue_chunk(s, s, m0, n0, tid, smem_base);
        asm volatile("cp.async.commit_group;" ::: "memory");
    }

    for (int i = 0; i < NCHUNK; i++) {
        asm volatile("cp.async.wait_group %0;" :: "n"(NSTAGE - 2) : "memory");
        __syncthreads();
        if (i + NSTAGE - 1 < NCHUNK)
            issue_chunk(i + NSTAGE - 1, (i + NSTAGE - 1) % NSTAGE, m0, n0, tid, smem_base);
        asm volatile("cp.async.commit_group;" ::: "memory");

        const char* sa = smem + (i % NSTAGE) * STG_BYTES;
        const char* sb = sa + A_BYTES;
#pragma unroll
        for (int p = 0; p < 2; p++) {
            uint4 af[4][2], bf[8];
#pragma unroll
            for (int ii = 0; ii < 4; ii++) {
                af[ii][0] = *(const uint4*)(sa + (aoff[ii][0] ^ (p << 6)));
                af[ii][1] = *(const uint4*)(sa + (aoff[ii][1] ^ (p << 6)));
            }
#pragma unroll
            for (int jj = 0; jj < 8; jj++)
                bf[jj] = *(const uint4*)(sb + (boff[jj] ^ (p << 6)));
#pragma unroll
            for (int ii = 0; ii < 4; ii++)
#pragma unroll
                for (int jj = 0; jj < 8; jj++) {
                    mma_tf32(acc[ii][jj],
                             af[ii][0].x, af[ii][1].x, af[ii][0].y, af[ii][1].y,
                             bf[jj].x, bf[jj].y);
                    mma_tf32(acc[ii][jj],
                             af[ii][0].z, af[ii][1].z, af[ii][0].w, af[ii][1].w,
                             bf[jj].z, bf[jj].w);
                }
        }
    }

#pragma unroll
    for (int j = 0; j < 8; j++) {
        int col = n0 + wn * 64 + j * 8 + 2 * c;
        float2 bb = *(const float2*)(bias + col);
#pragma unroll
        for (int i = 0; i < 4; i++) {
            int row = m0 + wm * 64 + i * 16 + rq;
            float2 lo = make_float2(acc[i][j][0] + bb.x, acc[i][j][1] + bb.y);
            float2 hi = make_float2(acc[i][j][2] + bb.x, acc[i][j][3] + bb.y);
            *(float2*)(out + (size_t)row * ODIM + col) = lo;
            *(float2*)(out + (size_t)(row + 8) * ODIM + col) = hi;
        }
    }
}

extern "C" void kernel_launch(void* const* d_in, const int* in_sizes, int n_in,
                              void* d_out, int out_size) {
    const float* x    = (const float*)d_in[0];
    const float* bW   = (const float*)d_in[1];
    const float* bb   = (const float*)d_in[2];
    const float* rW   = (const float*)d_in[3];
    const float* rb   = (const float*)d_in[4];
    const float* A    = (const float*)d_in[5];
    const float* Bm   = (const float*)d_in[6];
    const int*   emap = (const int*)d_in[7];
    float* out = (float*)d_out;

    static int configured = 0;
    if (!configured) {
        cudaFuncSetAttribute(main_kernel, cudaFuncAttributeMaxDynamicSharedMemorySize,
                             SMEM_BYTES);
        cudaFuncSetAttribute(hwr_kernel, cudaFuncAttributeMaxDynamicSharedMemorySize,
                             SMEMH_BYTES);
        configured = 1;
    }

    round_x_kernel<<<(MTOK * DDIM / 4) / 256, 256>>>(x);
    round_w_kernel<<<(ODIM * DDIM / 4) / 256, 256>>>(bW);
    ar_fill_kernel<<<(ERD * DDIM / 4) / 256, 256>>>(A);
    bcat_kernel<<<(ODIM * ERD + 255) / 256, 256>>>(Bm);
    logits_kernel<<<MTOK / 64, 256>>>(x, rW);
    hwr_kernel<<<MTOK / BMH, 256, SMEMH_BYTES>>>();
    w_kernel<<<MTOK / 256, 256>>>(rb, emap);
    scale_kernel<<<(MTOK * ERD / 4) / 256, 256>>>();
    dim3 grid(ODIM / BN, MTOK / BM);
    main_kernel<<<grid, 256, SMEM_BYTES>>>(bb, out);
}